// round 13
// baseline (speedup 1.0000x reference)
#include <cuda_runtime.h>
#include <cuda_bf16.h>
#include <math.h>
#include <stdint.h>

#define BB 4
#define LQ 128
#define LF 64
#define NW 2
#define NFR 8
#define EE 128
#define DD 128
#define VV 64
#define WF (NW*NFR)   // 16

// ---- output layout (concatenated in reference tuple order) ----
#define OUT_FRAGCODE  0
#define OUT_QUERYCODE (BB*WF*DD)
#define OUT_SELFATT   (2*BB*WF*DD)
#define OUT_GATE      (2*BB*WF*DD + BB*WF*LF)
#define OUT_QUERY     (OUT_GATE + BB*WF*LQ)

// ---- scratch ----
__device__ float g_fproj[BB*WF*LF*DD];   // projected fragment (b,wf,lf,d)
__device__ float g_qatt [BB*LQ*VV];      // q_att (b,lq,v)
__device__ float g_fatt [BB*WF*LF*VV];   // f_att (b,wf,lf,v)
__device__ float g_pmax [512*64*64];     // partial maxes [bwf*8+lqh*4+lfq][64][64] (8MB)
__device__ float g_probe[32];            // probe sink

// bf16 split helpers
__device__ __forceinline__ uint32_t pack_bf16x2(float lo_val, float hi_val) {
    uint32_t r;
    asm("cvt.rn.bf16x2.f32 %0, %1, %2;" : "=r"(r) : "f"(hi_val), "f"(lo_val));
    return r;
}
__device__ __forceinline__ float bf16lo_f32(uint32_t u) { return __uint_as_float(u << 16); }
__device__ __forceinline__ float bf16hi_f32(uint32_t u) { return __uint_as_float(u & 0xffff0000u); }
__device__ __forceinline__ void split2(float x0, float x1, uint32_t& hi, uint32_t& lo) {
    hi = pack_bf16x2(x0, x1);
    float r0 = x0 - bf16lo_f32(hi);
    float r1 = x1 - bf16hi_f32(hi);
    lo = pack_bf16x2(r0, r1);
}

// mma.sync m16n8k16 row.col f32.bf16.bf16.f32
__device__ __forceinline__ void mma16816(float* c, const uint32_t* a, const uint32_t* b) {
    asm volatile(
        "mma.sync.aligned.m16n8k16.row.col.f32.bf16.bf16.f32 "
        "{%0,%1,%2,%3}, {%4,%5,%6,%7}, {%8,%9}, {%0,%1,%2,%3};"
        : "+f"(c[0]), "+f"(c[1]), "+f"(c[2]), "+f"(c[3])
        : "r"(a[0]), "r"(a[1]), "r"(a[2]), "r"(a[3]), "r"(b[0]), "r"(b[1]));
}

// ============================================================
// Kernel A: fused projection + attention-weight GEMMs, tiled.
// ============================================================
__global__ void __launch_bounds__(256) k_projatt(
    const float* __restrict__ query, const float* __restrict__ frag,
    const float* __restrict__ W, const float* __restrict__ bias,
    const float* __restrict__ qattW, const float* __restrict__ fattW,
    float* __restrict__ outq) {
    extern __shared__ float s[];
    float* Wsh  = s;            // 16384
    float* AWsh = s + 16384;    // 8192
    float* xsh  = s + 24576;    // 1024
    float* psh  = s + 25600;    // 1024   total 26624 floats
    int g = blockIdx.x;
    int tid = threadIdx.x;
    bool isq = (g < 64);

    {
        const float4* Wv = (const float4*)W;
        float4* Ws = (float4*)Wsh;
        #pragma unroll
        for (int i = 0; i < 16; i++) Ws[tid + 256*i] = Wv[tid + 256*i];
        const float4* Av = (const float4*)(isq ? qattW : fattW);
        float4* As = (float4*)AWsh;
        #pragma unroll
        for (int i = 0; i < 8; i++) As[tid + 256*i] = Av[tid + 256*i];
        const float* src = isq ? (query + (size_t)g*8*EE)
                               : (frag  + (size_t)(g-64)*8*EE);
        ((float4*)xsh)[tid] = ((const float4*)src)[tid];
    }
    __syncthreads();

    {
        int j = tid & 127, rh = tid >> 7;
        float bj = __ldg(&bias[j]);
        float a0 = bj, a1 = bj, a2 = bj, a3 = bj;
        #pragma unroll 4
        for (int d = 0; d < EE; d++) {
            float w = Wsh[d*DD + j];
            a0 = fmaf(xsh[(rh+0)*EE + d], w, a0);
            a1 = fmaf(xsh[(rh+2)*EE + d], w, a1);
            a2 = fmaf(xsh[(rh+4)*EE + d], w, a2);
            a3 = fmaf(xsh[(rh+6)*EE + d], w, a3);
        }
        psh[(rh+0)*DD + j] = a0; psh[(rh+2)*DD + j] = a1;
        psh[(rh+4)*DD + j] = a2; psh[(rh+6)*DD + j] = a3;
        float* dst = isq ? (outq + (size_t)g*8*DD)
                         : (g_fproj + (size_t)(g-64)*8*DD);
        dst[(rh+0)*DD + j] = a0; dst[(rh+2)*DD + j] = a1;
        dst[(rh+4)*DD + j] = a2; dst[(rh+6)*DD + j] = a3;
    }
    __syncthreads();

    {
        int j2 = tid & 63, r2 = tid >> 6;
        float a0 = 0.f, a1 = 0.f;
        #pragma unroll 4
        for (int d = 0; d < DD; d++) {
            float w = AWsh[d*VV + j2];
            a0 = fmaf(psh[(r2+0)*DD + d], w, a0);
            a1 = fmaf(psh[(r2+4)*DD + d], w, a1);
        }
        float* dst = isq ? (g_qatt + (size_t)g*8*VV)
                         : (g_fatt + (size_t)(g-64)*8*VV);
        dst[(r2+0)*VV + j2] = a0;
        dst[(r2+4)*VV + j2] = a1;
    }
}

// ============================================================
// Kernel B: fragment self-attention softmax + frag_code
// ============================================================
__global__ void k_fragcode(const float* __restrict__ saW,
                           const float* __restrict__ fmask,
                           float* __restrict__ out) {
    int bwf = blockIdx.x;
    int w = (bwf % WF) / NFR;
    const float* fbase = g_fproj + (size_t)bwf*LF*DD;
    __shared__ float att[LF];
    __shared__ float s_inv;
    int t = threadIdx.x;
    if (t < LF) {
        const float* fr = fbase + t*DD;
        const float* sw = saW + w*DD;
        float acc = 0.f;
        #pragma unroll 8
        for (int d = 0; d < DD; d++) acc += fr[d]*sw[d];
        att[t] = expf(acc) * fmask[bwf*LF + t];
    }
    __syncthreads();
    if (t == 0) {
        float ss = 0.f;
        for (int l = 0; l < LF; l++) ss += att[l];
        s_inv = 1.f / (ss + 1e-7f);
    }
    __syncthreads();
    float inv = s_inv;
    if (t < LF) out[OUT_SELFATT + bwf*LF + t] = att[t]*inv;
    float acc = 0.f;
    #pragma unroll 8
    for (int l = 0; l < LF; l++) acc += att[l]*inv*fbase[l*DD + t];
    out[OUT_FRAGCODE + bwf*DD + t] = acc;
}

// ============================================================
// Probe: trivial kernel at launch index 2 so ncu's fixed
// index-3 capture lands on k_qf_mma.
// ============================================================
__global__ void k_probe() { g_probe[threadIdx.x] = 0.f; }

// ============================================================
// Kernel C (hot, HMMA): per (bwf, lq-half64, lf-quarter16):
//   partial max over lf of (f_att + q @ (f_lf ⊙ W_qf))
// Round-7 conversion layout + MMA addressing VERBATIM; added:
// double-buffered B' (buffer 1 aliases A-staging; safe via barrier
// ordering) -> ONE sync per lf, conversion overlaps MMA.
// 8 warps: warp = (m-strip 16 of 64) x (n-half 32 of 64).
// ============================================================
// smem word offsets
#define QW_WT   0                      // W transposed [64][130] = 8320
#define QW_AH   8320                   // [64][68] u32 = 4352  (aliased by Bh2 later)
#define QW_AL   (QW_AH + 4352)         //                      (aliased by Bl2 later)
#define QW_BH   (QW_AL + 4352)         // [64][68] u32 = 4352
#define QW_BL   (QW_BH + 4352)
#define QW_TOT  (QW_BL + 4352)         // 25728 words = 102912 B (2 blocks/SM ok)

__device__ __forceinline__ void conv_B(const float* __restrict__ Wt,
                                       const float* __restrict__ fptr,
                                       uint32_t* __restrict__ BhD,
                                       uint32_t* __restrict__ BlD, int tid) {
    for (int idx = tid; idx < 64*64; idx += 256) {
        int v = idx >> 6, cp = idx & 63;
        float2 wv = *(const float2*)&Wt[v*130 + cp*2];
        float2 fv = *(const float2*)&fptr[cp*2];
        uint32_t hi, lo;
        split2(wv.x*fv.x, wv.y*fv.y, hi, lo);
        BhD[v*68 + cp] = hi;
        BlD[v*68 + cp] = lo;
    }
}

__global__ void __launch_bounds__(256) k_qf_mma(
    const float* __restrict__ qfW, const float* __restrict__ outq) {
    extern __shared__ float s[];
    float* Wt = s + QW_WT;                       // [v][130] fp32
    uint32_t* Ah = (uint32_t*)(s + QW_AH);       // [row][68]
    uint32_t* Al = (uint32_t*)(s + QW_AL);
    uint32_t* Bh = (uint32_t*)(s + QW_BH);       // buffer 0
    uint32_t* Bl = (uint32_t*)(s + QW_BL);
    uint32_t* Bh2 = (uint32_t*)(s + QW_AH);      // buffer 1 (aliases A staging)
    uint32_t* Bl2 = (uint32_t*)(s + QW_AL);

    int blk = blockIdx.x;            // 512 = bwf(64) x lqh(2) x lfq(4)
    int lfq = blk & 3;
    int lqh = (blk >> 2) & 1;
    int bwf = blk >> 3;
    int b = bwf >> 4;
    int lfbase = lfq * 16;
    int tid = threadIdx.x, lane = tid & 31, wid = tid >> 5;
    int m0 = (wid & 3) * 16;         // m-strip within 64
    int n0 = (wid >> 2) * 32;        // n-half

    // stage W transposed: Wt[v][d]
    for (int idx = tid; idx < DD*VV; idx += 256) {
        int d = idx >> 6, v = idx & 63;
        Wt[v*130 + d] = qfW[idx];
    }
    // convert A (q tile 64x128) -> bf16 hi/lo words [row][68]
    for (int idx = tid; idx < 64*64; idx += 256) {
        int row = idx >> 6, cp = idx & 63;
        float2 qv = *(const float2*)&outq[((size_t)(b*LQ + lqh*64 + row))*DD + cp*2];
        uint32_t hi, lo;
        split2(qv.x, qv.y, hi, lo);
        Ah[row*68 + cp] = hi;
        Al[row*68 + cp] = lo;
    }
    __syncthreads();

    // load A fragments (register-resident for all lf)
    uint32_t ah[8][4], al[8][4];
    {
        int r = m0 + (lane >> 2);
        #pragma unroll
        for (int k = 0; k < 8; k++) {
            int c = k*8 + (lane & 3);
            ah[k][0] = Ah[r*68 + c];       ah[k][1] = Ah[(r+8)*68 + c];
            ah[k][2] = Ah[r*68 + c + 4];   ah[k][3] = Ah[(r+8)*68 + c + 4];
            al[k][0] = Al[r*68 + c];       al[k][1] = Al[(r+8)*68 + c];
            al[k][2] = Al[r*68 + c + 4];   al[k][3] = Al[(r+8)*68 + c + 4];
        }
    }

    // prologue: convert B'(lfbase) into buffer 0 (non-aliased)
    conv_B(Wt, g_fproj + ((size_t)bwf*LF + lfbase)*DD, Bh, Bl, tid);
    __syncthreads();   // all A-frag loads done; Bh/Bl ready; alias now safe

    float mx[4][4];
    #pragma unroll
    for (int t = 0; t < 4; t++)
        #pragma unroll
        for (int i = 0; i < 4; i++) mx[t][i] = -INFINITY;

    for (int k16 = 0; k16 < 16; k16++) {
        int lf = lfbase + k16;
        uint32_t* Bhc = (k16 & 1) ? Bh2 : Bh;
        uint32_t* Blc = (k16 & 1) ? Bl2 : Bl;

        // convert next lf into the other buffer (overlaps MMA below via ILP)
        if (k16 < 15) {
            uint32_t* Bhn = (k16 & 1) ? Bh : Bh2;
            uint32_t* Bln = (k16 & 1) ? Bl : Bl2;
            conv_B(Wt, g_fproj + ((size_t)bwf*LF + lf + 1)*DD, Bhn, Bln, tid);
        }

        // 3-pass split GEMM, C[16x32] per warp
        float cc[4][4];
        #pragma unroll
        for (int t = 0; t < 4; t++)
            #pragma unroll
            for (int i = 0; i < 4; i++) cc[t][i] = 0.f;

        #pragma unroll
        for (int k = 0; k < 8; k++) {
            #pragma unroll
            for (int t = 0; t < 4; t++) {
                int v = n0 + t*8 + (lane >> 2);
                int c = k*8 + (lane & 3);
                uint32_t bh[2], bl[2];
                bh[0] = Bhc[v*68 + c];  bh[1] = Bhc[v*68 + c + 4];
                bl[0] = Blc[v*68 + c];  bl[1] = Blc[v*68 + c + 4];
                mma16816(cc[t], ah[k], bh);
                mma16816(cc[t], ah[k], bl);
                mma16816(cc[t], al[k], bh);
            }
        }

        // running max of (cc + f_att)
        const float* fa = g_fatt + ((size_t)bwf*LF + lf)*VV;
        #pragma unroll
        for (int t = 0; t < 4; t++) {
            int col = n0 + t*8 + (lane & 3)*2;
            float2 f2 = *(const float2*)&fa[col];
            mx[t][0] = fmaxf(mx[t][0], cc[t][0] + f2.x);
            mx[t][1] = fmaxf(mx[t][1], cc[t][1] + f2.y);
            mx[t][2] = fmaxf(mx[t][2], cc[t][2] + f2.x);
            mx[t][3] = fmaxf(mx[t][3], cc[t][3] + f2.y);
        }

        __syncthreads();   // MMA reads of Bhc done; next conversion may overwrite
    }

    // write partial-max tile [64][64]
    float* outp = g_pmax + (size_t)blk * 4096;
    int r0 = m0 + (lane >> 2);
    #pragma unroll
    for (int t = 0; t < 4; t++) {
        int col = n0 + t*8 + (lane & 3)*2;
        *(float2*)&outp[r0*64 + col]     = make_float2(mx[t][0], mx[t][1]);
        *(float2*)&outp[(r0+8)*64 + col] = make_float2(mx[t][2], mx[t][3]);
    }
}

// ============================================================
// Kernel D: fused finalize, 512 threads, ONE launch.
// ============================================================
__global__ void __launch_bounds__(512) k_fin(
    const float* __restrict__ gate_w,
    const float* __restrict__ val_w,
    const float* __restrict__ qmask,
    const float* __restrict__ outq,
    float* __restrict__ out) {
    int bwf = blockIdx.x;
    int b = bwf >> 4;
    int tid = threadIdx.x;
    int lq = tid & 127, vq = tid >> 7;
    __shared__ float gsh[4][LQ];
    __shared__ float vsh[4][LQ];
    __shared__ float esh[LQ];
    __shared__ float red[LQ];
    __shared__ float inv_s;

    {
        int lqh = lq >> 6, r = lq & 63;
        const float* base = g_pmax + ((size_t)(bwf*8 + lqh*4)) * 4096 + r*64;
        const float4* qa = (const float4*)(g_qatt + (size_t)(b*LQ + lq)*VV);
        const float4* gw = (const float4*)gate_w;
        const float4* vw = (const float4*)val_w;
        float gs = 0.f, vs = 0.f;
        #pragma unroll
        for (int i = vq*4; i < vq*4 + 4; i++) {
            float4 a0 = *(const float4*)&base[i*4];
            float4 a1 = *(const float4*)&base[4096 + i*4];
            float4 a2 = *(const float4*)&base[2*4096 + i*4];
            float4 a3 = *(const float4*)&base[3*4096 + i*4];
            float4 q = qa[i], g4 = gw[i], v4 = vw[i];
            float mxv = fmaxf(fmaxf(a0.x, a1.x), fmaxf(a2.x, a3.x)) + q.x;
            float myv = fmaxf(fmaxf(a0.y, a1.y), fmaxf(a2.y, a3.y)) + q.y;
            float mzv = fmaxf(fmaxf(a0.z, a1.z), fmaxf(a2.z, a3.z)) + q.z;
            float mwv = fmaxf(fmaxf(a0.w, a1.w), fmaxf(a2.w, a3.w)) + q.w;
            gs += mxv*g4.x + myv*g4.y + mzv*g4.z + mwv*g4.w;
            vs += mxv*v4.x + myv*v4.y + mzv*v4.z + mwv*v4.w;
        }
        gsh[vq][lq] = gs;
        vsh[vq][lq] = vs;
    }
    __syncthreads();

    if (tid < LQ) {
        float gsum = gsh[0][tid] + gsh[1][tid] + gsh[2][tid] + gsh[3][tid];
        float vsum = vsh[0][tid] + vsh[1][tid] + vsh[2][tid] + vsh[3][tid];
        float qm = qmask[b*LQ + tid];
        out[OUT_GATE + bwf*LQ + tid] = (1.f / (1.f + expf(-gsum))) * qm;
        float e2 = expf(vsum) * qm;
        esh[tid] = e2;
        red[tid] = e2;
    }
    __syncthreads();
    #pragma unroll
    for (int off = 64; off > 0; off >>= 1) {
        if (tid < off) red[tid] += red[tid + off];
        __syncthreads();
    }
    if (tid == 0) inv_s = 1.f / (red[0] + 1e-7f);
    __syncthreads();

    {
        int d = lq;
        const float* qb = outq + ((size_t)(b*LQ + vq*32))*DD + d;
        float acc = 0.f;
        #pragma unroll 8
        for (int l = 0; l < 32; l++)
            acc = fmaf(esh[vq*32 + l], qb[(size_t)l*DD], acc);
        gsh[vq][d] = acc;
    }
    __syncthreads();
    if (tid < LQ) {
        float qc = gsh[0][tid] + gsh[1][tid] + gsh[2][tid] + gsh[3][tid];
        out[OUT_QUERYCODE + bwf*DD + tid] = qc * inv_s;
    }
}

// ============================================================
extern "C" void kernel_launch(void* const* d_in, const int* in_sizes, int n_in,
                              void* d_out, int out_size) {
    const float* query    = (const float*)d_in[0];
    const float* fragment = (const float*)d_in[1];
    const float* qmask    = (const float*)d_in[2];
    const float* fmask    = (const float*)d_in[3];
    const float* projW    = (const float*)d_in[4];
    const float* projb    = (const float*)d_in[5];
    const float* saW      = (const float*)d_in[6];
    const float* qattW    = (const float*)d_in[7];
    const float* fattW    = (const float*)d_in[8];
    const float* qfW      = (const float*)d_in[9];
    const float* gatew    = (const float*)d_in[10];
    const float* valw     = (const float*)d_in[11];
    float* out = (float*)d_out;
    float* outq = out + OUT_QUERY;

    const int smemPA = 26624 * (int)sizeof(float);   // 106496
    const int smemQF = QW_TOT * (int)sizeof(float);  // 102912
    cudaFuncSetAttribute(k_projatt, cudaFuncAttributeMaxDynamicSharedMemorySize, smemPA);
    cudaFuncSetAttribute(k_qf_mma, cudaFuncAttributeMaxDynamicSharedMemorySize, smemQF);

    k_projatt<<<576, 256, smemPA>>>(query, fragment, projW, projb, qattW, fattW, outq);  // idx 0
    k_fragcode<<<BB*WF, 128>>>(saW, fmask, out);                                          // idx 1
    k_probe<<<1, 32>>>();                                                                 // idx 2
    k_qf_mma<<<512, 256, smemQF>>>(qfW, outq);                                            // idx 3 (profiled)
    k_fin<<<BB*WF, 512>>>(gatew, valw, qmask, outq, out);                                 // idx 4
}

// round 14
// speedup vs baseline: 1.0128x; 1.0128x over previous
#include <cuda_runtime.h>
#include <cuda_bf16.h>
#include <math.h>
#include <stdint.h>

#define BB 4
#define LQ 128
#define LF 64
#define NW 2
#define NFR 8
#define EE 128
#define DD 128
#define VV 64
#define WF (NW*NFR)   // 16

// ---- output layout (concatenated in reference tuple order) ----
#define OUT_FRAGCODE  0
#define OUT_QUERYCODE (BB*WF*DD)
#define OUT_SELFATT   (2*BB*WF*DD)
#define OUT_GATE      (2*BB*WF*DD + BB*WF*LF)
#define OUT_QUERY     (OUT_GATE + BB*WF*LQ)

// ---- scratch ----
__device__ float g_fproj[BB*WF*LF*DD];   // projected fragment (b,wf,lf,d)
__device__ float g_qatt [BB*LQ*VV];      // q_att (b,lq,v)
__device__ float g_fatt [BB*WF*LF*VV];   // f_att (b,wf,lf,v)
__device__ float g_pmax [256*LQ*VV];     // partial maxes [bwf*4+lfq][128][64] (8MB)
__device__ float g_probe[32];            // probe sink

// bf16 split helpers
__device__ __forceinline__ uint32_t pack_bf16x2(float lo_val, float hi_val) {
    uint32_t r;
    asm("cvt.rn.bf16x2.f32 %0, %1, %2;" : "=r"(r) : "f"(hi_val), "f"(lo_val));
    return r;
}
__device__ __forceinline__ float bf16lo_f32(uint32_t u) { return __uint_as_float(u << 16); }
__device__ __forceinline__ float bf16hi_f32(uint32_t u) { return __uint_as_float(u & 0xffff0000u); }
__device__ __forceinline__ void split2(float x0, float x1, uint32_t& hi, uint32_t& lo) {
    hi = pack_bf16x2(x0, x1);
    float r0 = x0 - bf16lo_f32(hi);
    float r1 = x1 - bf16hi_f32(hi);
    lo = pack_bf16x2(r0, r1);
}

// mma.sync m16n8k16 row.col f32.bf16.bf16.f32
__device__ __forceinline__ void mma16816(float* c, const uint32_t* a, const uint32_t* b) {
    asm volatile(
        "mma.sync.aligned.m16n8k16.row.col.f32.bf16.bf16.f32 "
        "{%0,%1,%2,%3}, {%4,%5,%6,%7}, {%8,%9}, {%0,%1,%2,%3};"
        : "+f"(c[0]), "+f"(c[1]), "+f"(c[2]), "+f"(c[3])
        : "r"(a[0]), "r"(a[1]), "r"(a[2]), "r"(a[3]), "r"(b[0]), "r"(b[1]));
}

// ============================================================
// Kernel A: fused projection + attention-weight GEMMs, tiled.
// ============================================================
__global__ void __launch_bounds__(256) k_projatt(
    const float* __restrict__ query, const float* __restrict__ frag,
    const float* __restrict__ W, const float* __restrict__ bias,
    const float* __restrict__ qattW, const float* __restrict__ fattW,
    float* __restrict__ outq) {
    extern __shared__ float s[];
    float* Wsh  = s;            // 16384
    float* AWsh = s + 16384;    // 8192
    float* xsh  = s + 24576;    // 1024
    float* psh  = s + 25600;    // 1024   total 26624 floats
    int g = blockIdx.x;
    int tid = threadIdx.x;
    bool isq = (g < 64);

    {
        const float4* Wv = (const float4*)W;
        float4* Ws = (float4*)Wsh;
        #pragma unroll
        for (int i = 0; i < 16; i++) Ws[tid + 256*i] = Wv[tid + 256*i];
        const float4* Av = (const float4*)(isq ? qattW : fattW);
        float4* As = (float4*)AWsh;
        #pragma unroll
        for (int i = 0; i < 8; i++) As[tid + 256*i] = Av[tid + 256*i];
        const float* src = isq ? (query + (size_t)g*8*EE)
                               : (frag  + (size_t)(g-64)*8*EE);
        ((float4*)xsh)[tid] = ((const float4*)src)[tid];
    }
    __syncthreads();

    {
        int j = tid & 127, rh = tid >> 7;
        float bj = __ldg(&bias[j]);
        float a0 = bj, a1 = bj, a2 = bj, a3 = bj;
        #pragma unroll 4
        for (int d = 0; d < EE; d++) {
            float w = Wsh[d*DD + j];
            a0 = fmaf(xsh[(rh+0)*EE + d], w, a0);
            a1 = fmaf(xsh[(rh+2)*EE + d], w, a1);
            a2 = fmaf(xsh[(rh+4)*EE + d], w, a2);
            a3 = fmaf(xsh[(rh+6)*EE + d], w, a3);
        }
        psh[(rh+0)*DD + j] = a0; psh[(rh+2)*DD + j] = a1;
        psh[(rh+4)*DD + j] = a2; psh[(rh+6)*DD + j] = a3;
        float* dst = isq ? (outq + (size_t)g*8*DD)
                         : (g_fproj + (size_t)(g-64)*8*DD);
        dst[(rh+0)*DD + j] = a0; dst[(rh+2)*DD + j] = a1;
        dst[(rh+4)*DD + j] = a2; dst[(rh+6)*DD + j] = a3;
    }
    __syncthreads();

    {
        int j2 = tid & 63, r2 = tid >> 6;
        float a0 = 0.f, a1 = 0.f;
        #pragma unroll 4
        for (int d = 0; d < DD; d++) {
            float w = AWsh[d*VV + j2];
            a0 = fmaf(psh[(r2+0)*DD + d], w, a0);
            a1 = fmaf(psh[(r2+4)*DD + d], w, a1);
        }
        float* dst = isq ? (g_qatt + (size_t)g*8*VV)
                         : (g_fatt + (size_t)(g-64)*8*VV);
        dst[(r2+0)*VV + j2] = a0;
        dst[(r2+4)*VV + j2] = a1;
    }
}

// ============================================================
// Kernel B: fragment self-attention softmax + frag_code
// ============================================================
__global__ void k_fragcode(const float* __restrict__ saW,
                           const float* __restrict__ fmask,
                           float* __restrict__ out) {
    int bwf = blockIdx.x;
    int w = (bwf % WF) / NFR;
    const float* fbase = g_fproj + (size_t)bwf*LF*DD;
    __shared__ float att[LF];
    __shared__ float s_inv;
    int t = threadIdx.x;
    if (t < LF) {
        const float* fr = fbase + t*DD;
        const float* sw = saW + w*DD;
        float acc = 0.f;
        #pragma unroll 8
        for (int d = 0; d < DD; d++) acc += fr[d]*sw[d];
        att[t] = expf(acc) * fmask[bwf*LF + t];
    }
    __syncthreads();
    if (t == 0) {
        float ss = 0.f;
        for (int l = 0; l < LF; l++) ss += att[l];
        s_inv = 1.f / (ss + 1e-7f);
    }
    __syncthreads();
    float inv = s_inv;
    if (t < LF) out[OUT_SELFATT + bwf*LF + t] = att[t]*inv;
    float acc = 0.f;
    #pragma unroll 8
    for (int l = 0; l < LF; l++) acc += att[l]*inv*fbase[l*DD + t];
    out[OUT_FRAGCODE + bwf*DD + t] = acc;
}

// ============================================================
// Probe: trivial kernel at launch index 2 so ncu's fixed
// index-3 capture lands on k_qf_mma.
// ============================================================
__global__ void k_probe() { g_probe[threadIdx.x] = 0.f; }

// ============================================================
// Kernel C (hot, HMMA): per (bwf, lf-quarter16), FULL M=128:
//   partial max over lf of (f_att + q @ (f_lf ⊙ W_qf))
// B' = f⊙W converted ONCE per (bwf,lf) (was twice with split lq
// halves) — conversion work and barrier count per MMA-op halved.
// Register budget fix vs round-9 merge: only A_hi fragments are
// register-resident (32 regs); A_lo fragments loaded from smem
// per k (4 LDS.32 under 12 HMMA). ~90 regs < 128 cap, no spills.
// 16 warps: warp = (m-strip 16 of 128) x (n-half 32 of 64).
// Conversion layout + MMA addressing identical to round 7.
// ============================================================
// smem word offsets
#define QW_WT   0                       // W transposed [64][130] = 8320
#define QW_AH   8320                    // [128][68] u32 = 8704
#define QW_AL   (QW_AH + 8704)          // [128][68] u32 = 8704
#define QW_BH   (QW_AL + 8704)          // [64][68] u32 = 4352
#define QW_BL   (QW_BH + 4352)
#define QW_TOT  (QW_BL + 4352)          // 34432 words = 137728 B

__global__ void __launch_bounds__(512) k_qf_mma(
    const float* __restrict__ qfW, const float* __restrict__ outq) {
    extern __shared__ float s[];
    float* Wt = s + QW_WT;                       // [v][130] fp32
    uint32_t* Ah = (uint32_t*)(s + QW_AH);       // [row][68]
    uint32_t* Al = (uint32_t*)(s + QW_AL);
    uint32_t* Bh = (uint32_t*)(s + QW_BH);       // [v][68]
    uint32_t* Bl = (uint32_t*)(s + QW_BL);

    int blk = blockIdx.x;            // 256 = bwf(64) x lfq(4)
    int lfq = blk & 3;
    int bwf = blk >> 2;
    int b = bwf >> 4;
    int lfbase = lfq * 16;
    int tid = threadIdx.x, lane = tid & 31, wid = tid >> 5;
    int m0 = (wid & 7) * 16;         // m-strip within 128
    int n0 = (wid >> 3) * 32;        // n-half

    // stage W transposed: Wt[v][d]
    for (int idx = tid; idx < DD*VV; idx += 512) {
        int d = idx >> 6, v = idx & 63;
        Wt[v*130 + d] = qfW[idx];
    }
    // convert A (q tile 128x128) -> bf16 hi/lo words [row][68]
    for (int idx = tid; idx < 128*64; idx += 512) {
        int row = idx >> 6, cp = idx & 63;
        float2 qv = *(const float2*)&outq[((size_t)(b*LQ + row))*DD + cp*2];
        uint32_t hi, lo;
        split2(qv.x, qv.y, hi, lo);
        Ah[row*68 + cp] = hi;
        Al[row*68 + cp] = lo;
    }
    __syncthreads();

    // load A_hi fragments only (register-resident for all lf); A_lo stays in smem
    uint32_t ah[8][4];
    int rfrag = m0 + (lane >> 2);
    {
        #pragma unroll
        for (int k = 0; k < 8; k++) {
            int c = k*8 + (lane & 3);
            ah[k][0] = Ah[rfrag*68 + c];       ah[k][1] = Ah[(rfrag+8)*68 + c];
            ah[k][2] = Ah[rfrag*68 + c + 4];   ah[k][3] = Ah[(rfrag+8)*68 + c + 4];
        }
    }

    float mx[4][4];
    #pragma unroll
    for (int t = 0; t < 4; t++)
        #pragma unroll
        for (int i = 0; i < 4; i++) mx[t][i] = -INFINITY;

    for (int k16 = 0; k16 < 16; k16++) {
        int lf = lfbase + k16;
        __syncthreads();     // prior-iter B reads complete before overwrite

        // convert B' = f ⊙ W -> bf16 hi/lo [v][68] (once per (bwf,lf))
        const float* fptr = g_fproj + ((size_t)bwf*LF + lf)*DD;
        for (int idx = tid; idx < 64*64; idx += 512) {
            int v = idx >> 6, cp = idx & 63;
            float2 wv = *(const float2*)&Wt[v*130 + cp*2];
            float2 fv = *(const float2*)&fptr[cp*2];
            uint32_t hi, lo;
            split2(wv.x*fv.x, wv.y*fv.y, hi, lo);
            Bh[v*68 + cp] = hi;
            Bl[v*68 + cp] = lo;
        }
        __syncthreads();

        // 3-pass split GEMM, C[16x32] per warp
        float cc[4][4];
        #pragma unroll
        for (int t = 0; t < 4; t++)
            #pragma unroll
            for (int i = 0; i < 4; i++) cc[t][i] = 0.f;

        #pragma unroll
        for (int k = 0; k < 8; k++) {
            int c = k*8 + (lane & 3);
            uint32_t alk[4];
            alk[0] = Al[rfrag*68 + c];       alk[1] = Al[(rfrag+8)*68 + c];
            alk[2] = Al[rfrag*68 + c + 4];   alk[3] = Al[(rfrag+8)*68 + c + 4];
            #pragma unroll
            for (int t = 0; t < 4; t++) {
                int v = n0 + t*8 + (lane >> 2);
                uint32_t bh[2], bl[2];
                bh[0] = Bh[v*68 + c];  bh[1] = Bh[v*68 + c + 4];
                bl[0] = Bl[v*68 + c];  bl[1] = Bl[v*68 + c + 4];
                mma16816(cc[t], ah[k], bh);
                mma16816(cc[t], ah[k], bl);
                mma16816(cc[t], alk,   bh);
            }
        }

        // running max of (cc + f_att)
        const float* fa = g_fatt + ((size_t)bwf*LF + lf)*VV;
        #pragma unroll
        for (int t = 0; t < 4; t++) {
            int col = n0 + t*8 + (lane & 3)*2;
            float2 f2 = *(const float2*)&fa[col];
            mx[t][0] = fmaxf(mx[t][0], cc[t][0] + f2.x);
            mx[t][1] = fmaxf(mx[t][1], cc[t][1] + f2.y);
            mx[t][2] = fmaxf(mx[t][2], cc[t][2] + f2.x);
            mx[t][3] = fmaxf(mx[t][3], cc[t][3] + f2.y);
        }
    }

    // write partial-max tile [128][64]
    float* outp = g_pmax + (size_t)blk * (LQ*VV);
    #pragma unroll
    for (int t = 0; t < 4; t++) {
        int col = n0 + t*8 + (lane & 3)*2;
        *(float2*)&outp[rfrag*64 + col]     = make_float2(mx[t][0], mx[t][1]);
        *(float2*)&outp[(rfrag+8)*64 + col] = make_float2(mx[t][2], mx[t][3]);
    }
}

// ============================================================
// Kernel D: fused finalize, 512 threads, ONE launch.
// pmax layout now [bwf*4+lfq][128][64].
// ============================================================
__global__ void __launch_bounds__(512) k_fin(
    const float* __restrict__ gate_w,
    const float* __restrict__ val_w,
    const float* __restrict__ qmask,
    const float* __restrict__ outq,
    float* __restrict__ out) {
    int bwf = blockIdx.x;
    int b = bwf >> 4;
    int tid = threadIdx.x;
    int lq = tid & 127, vq = tid >> 7;
    __shared__ float gsh[4][LQ];
    __shared__ float vsh[4][LQ];
    __shared__ float esh[LQ];
    __shared__ float red[LQ];
    __shared__ float inv_s;

    {
        const float* base = g_pmax + (size_t)(bwf*4) * (LQ*VV) + lq*VV;
        const float4* qa = (const float4*)(g_qatt + (size_t)(b*LQ + lq)*VV);
        const float4* gw = (const float4*)gate_w;
        const float4* vw = (const float4*)val_w;
        float gs = 0.f, vs = 0.f;
        #pragma unroll
        for (int i = vq*4; i < vq*4 + 4; i++) {
            float4 a0 = *(const float4*)&base[i*4];
            float4 a1 = *(const float4*)&base[LQ*VV + i*4];
            float4 a2 = *(const float4*)&base[2*LQ*VV + i*4];
            float4 a3 = *(const float4*)&base[3*LQ*VV + i*4];
            float4 q = qa[i], g4 = gw[i], v4 = vw[i];
            float mxv = fmaxf(fmaxf(a0.x, a1.x), fmaxf(a2.x, a3.x)) + q.x;
            float myv = fmaxf(fmaxf(a0.y, a1.y), fmaxf(a2.y, a3.y)) + q.y;
            float mzv = fmaxf(fmaxf(a0.z, a1.z), fmaxf(a2.z, a3.z)) + q.z;
            float mwv = fmaxf(fmaxf(a0.w, a1.w), fmaxf(a2.w, a3.w)) + q.w;
            gs += mxv*g4.x + myv*g4.y + mzv*g4.z + mwv*g4.w;
            vs += mxv*v4.x + myv*v4.y + mzv*v4.z + mwv*v4.w;
        }
        gsh[vq][lq] = gs;
        vsh[vq][lq] = vs;
    }
    __syncthreads();

    if (tid < LQ) {
        float gsum = gsh[0][tid] + gsh[1][tid] + gsh[2][tid] + gsh[3][tid];
        float vsum = vsh[0][tid] + vsh[1][tid] + vsh[2][tid] + vsh[3][tid];
        float qm = qmask[b*LQ + tid];
        out[OUT_GATE + bwf*LQ + tid] = (1.f / (1.f + expf(-gsum))) * qm;
        float e2 = expf(vsum) * qm;
        esh[tid] = e2;
        red[tid] = e2;
    }
    __syncthreads();
    #pragma unroll
    for (int off = 64; off > 0; off >>= 1) {
        if (tid < off) red[tid] += red[tid + off];
        __syncthreads();
    }
    if (tid == 0) inv_s = 1.f / (red[0] + 1e-7f);
    __syncthreads();

    {
        int d = lq;
        const float* qb = outq + ((size_t)(b*LQ + vq*32))*DD + d;
        float acc = 0.f;
        #pragma unroll 8
        for (int l = 0; l < 32; l++)
            acc = fmaf(esh[vq*32 + l], qb[(size_t)l*DD], acc);
        gsh[vq][d] = acc;
    }
    __syncthreads();
    if (tid < LQ) {
        float qc = gsh[0][tid] + gsh[1][tid] + gsh[2][tid] + gsh[3][tid];
        out[OUT_QUERYCODE + bwf*DD + tid] = qc * inv_s;
    }
}

// ============================================================
extern "C" void kernel_launch(void* const* d_in, const int* in_sizes, int n_in,
                              void* d_out, int out_size) {
    const float* query    = (const float*)d_in[0];
    const float* fragment = (const float*)d_in[1];
    const float* qmask    = (const float*)d_in[2];
    const float* fmask    = (const float*)d_in[3];
    const float* projW    = (const float*)d_in[4];
    const float* projb    = (const float*)d_in[5];
    const float* saW      = (const float*)d_in[6];
    const float* qattW    = (const float*)d_in[7];
    const float* fattW    = (const float*)d_in[8];
    const float* qfW      = (const float*)d_in[9];
    const float* gatew    = (const float*)d_in[10];
    const float* valw     = (const float*)d_in[11];
    float* out = (float*)d_out;
    float* outq = out + OUT_QUERY;

    const int smemPA = 26624 * (int)sizeof(float);   // 106496
    const int smemQF = QW_TOT * (int)sizeof(float);  // 137728
    cudaFuncSetAttribute(k_projatt, cudaFuncAttributeMaxDynamicSharedMemorySize, smemPA);
    cudaFuncSetAttribute(k_qf_mma, cudaFuncAttributeMaxDynamicSharedMemorySize, smemQF);

    k_projatt<<<576, 256, smemPA>>>(query, fragment, projW, projb, qattW, fattW, outq);  // idx 0
    k_fragcode<<<BB*WF, 128>>>(saW, fmask, out);                                          // idx 1
    k_probe<<<1, 32>>>();                                                                 // idx 2
    k_qf_mma<<<256, 512, smemQF>>>(qfW, outq);                                            // idx 3 (profiled)
    k_fin<<<BB*WF, 512>>>(gatew, valw, qmask, outq, out);                                 // idx 4
}

// round 15
// speedup vs baseline: 1.0651x; 1.0517x over previous
#include <cuda_runtime.h>
#include <cuda_bf16.h>
#include <math.h>
#include <stdint.h>

#define BB 4
#define LQ 128
#define LF 64
#define NW 2
#define NFR 8
#define EE 128
#define DD 128
#define VV 64
#define WF (NW*NFR)   // 16

// ---- output layout (concatenated in reference tuple order) ----
#define OUT_FRAGCODE  0
#define OUT_QUERYCODE (BB*WF*DD)
#define OUT_SELFATT   (2*BB*WF*DD)
#define OUT_GATE      (2*BB*WF*DD + BB*WF*LF)
#define OUT_QUERY     (OUT_GATE + BB*WF*LQ)

// ---- scratch ----
__device__ float g_fproj[BB*WF*LF*DD];   // projected fragment (b,wf,lf,d)
__device__ float g_qatt [BB*LQ*VV];      // q_att (b,lq,v)
__device__ float g_fatt [BB*WF*LF*VV];   // f_att (b,wf,lf,v)
__device__ float g_pmax [256*LQ*VV];     // partial maxes [bwf*4+lfq][128][64] (8MB)
__device__ float g_probe[32];            // probe sink

// bf16 split helpers
__device__ __forceinline__ uint32_t pack_bf16x2(float lo_val, float hi_val) {
    uint32_t r;
    asm("cvt.rn.bf16x2.f32 %0, %1, %2;" : "=r"(r) : "f"(hi_val), "f"(lo_val));
    return r;
}
__device__ __forceinline__ float bf16lo_f32(uint32_t u) { return __uint_as_float(u << 16); }
__device__ __forceinline__ float bf16hi_f32(uint32_t u) { return __uint_as_float(u & 0xffff0000u); }
__device__ __forceinline__ void split2(float x0, float x1, uint32_t& hi, uint32_t& lo) {
    hi = pack_bf16x2(x0, x1);
    float r0 = x0 - bf16lo_f32(hi);
    float r1 = x1 - bf16hi_f32(hi);
    lo = pack_bf16x2(r0, r1);
}

// mma.sync m16n8k16 row.col f32.bf16.bf16.f32
__device__ __forceinline__ void mma16816(float* c, const uint32_t* a, const uint32_t* b) {
    asm volatile(
        "mma.sync.aligned.m16n8k16.row.col.f32.bf16.bf16.f32 "
        "{%0,%1,%2,%3}, {%4,%5,%6,%7}, {%8,%9}, {%0,%1,%2,%3};"
        : "+f"(c[0]), "+f"(c[1]), "+f"(c[2]), "+f"(c[3])
        : "r"(a[0]), "r"(a[1]), "r"(a[2]), "r"(a[3]), "r"(b[0]), "r"(b[1]));
}

// named barriers (CUTLASS producer/consumer pattern)
#define BAR_SYNC(id, cnt)   asm volatile("bar.sync %0, %1;"   :: "r"(id), "r"(cnt) : "memory")
#define BAR_ARRIVE(id, cnt) asm volatile("bar.arrive %0, %1;" :: "r"(id), "r"(cnt) : "memory")

// ============================================================
// Kernel A: fused projection + attention-weight GEMMs, tiled.
// ============================================================
__global__ void __launch_bounds__(256) k_projatt(
    const float* __restrict__ query, const float* __restrict__ frag,
    const float* __restrict__ W, const float* __restrict__ bias,
    const float* __restrict__ qattW, const float* __restrict__ fattW,
    float* __restrict__ outq) {
    extern __shared__ float s[];
    float* Wsh  = s;            // 16384
    float* AWsh = s + 16384;    // 8192
    float* xsh  = s + 24576;    // 1024
    float* psh  = s + 25600;    // 1024   total 26624 floats
    int g = blockIdx.x;
    int tid = threadIdx.x;
    bool isq = (g < 64);

    {
        const float4* Wv = (const float4*)W;
        float4* Ws = (float4*)Wsh;
        #pragma unroll
        for (int i = 0; i < 16; i++) Ws[tid + 256*i] = Wv[tid + 256*i];
        const float4* Av = (const float4*)(isq ? qattW : fattW);
        float4* As = (float4*)AWsh;
        #pragma unroll
        for (int i = 0; i < 8; i++) As[tid + 256*i] = Av[tid + 256*i];
        const float* src = isq ? (query + (size_t)g*8*EE)
                               : (frag  + (size_t)(g-64)*8*EE);
        ((float4*)xsh)[tid] = ((const float4*)src)[tid];
    }
    __syncthreads();

    {
        int j = tid & 127, rh = tid >> 7;
        float bj = __ldg(&bias[j]);
        float a0 = bj, a1 = bj, a2 = bj, a3 = bj;
        #pragma unroll 4
        for (int d = 0; d < EE; d++) {
            float w = Wsh[d*DD + j];
            a0 = fmaf(xsh[(rh+0)*EE + d], w, a0);
            a1 = fmaf(xsh[(rh+2)*EE + d], w, a1);
            a2 = fmaf(xsh[(rh+4)*EE + d], w, a2);
            a3 = fmaf(xsh[(rh+6)*EE + d], w, a3);
        }
        psh[(rh+0)*DD + j] = a0; psh[(rh+2)*DD + j] = a1;
        psh[(rh+4)*DD + j] = a2; psh[(rh+6)*DD + j] = a3;
        float* dst = isq ? (outq + (size_t)g*8*DD)
                         : (g_fproj + (size_t)(g-64)*8*DD);
        dst[(rh+0)*DD + j] = a0; dst[(rh+2)*DD + j] = a1;
        dst[(rh+4)*DD + j] = a2; dst[(rh+6)*DD + j] = a3;
    }
    __syncthreads();

    {
        int j2 = tid & 63, r2 = tid >> 6;
        float a0 = 0.f, a1 = 0.f;
        #pragma unroll 4
        for (int d = 0; d < DD; d++) {
            float w = AWsh[d*VV + j2];
            a0 = fmaf(psh[(r2+0)*DD + d], w, a0);
            a1 = fmaf(psh[(r2+4)*DD + d], w, a1);
        }
        float* dst = isq ? (g_qatt + (size_t)g*8*VV)
                         : (g_fatt + (size_t)(g-64)*8*VV);
        dst[(r2+0)*VV + j2] = a0;
        dst[(r2+4)*VV + j2] = a1;
    }
}

// ============================================================
// Kernel B: fragment self-attention softmax + frag_code
// ============================================================
__global__ void k_fragcode(const float* __restrict__ saW,
                           const float* __restrict__ fmask,
                           float* __restrict__ out) {
    int bwf = blockIdx.x;
    int w = (bwf % WF) / NFR;
    const float* fbase = g_fproj + (size_t)bwf*LF*DD;
    __shared__ float att[LF];
    __shared__ float s_inv;
    int t = threadIdx.x;
    if (t < LF) {
        const float* fr = fbase + t*DD;
        const float* sw = saW + w*DD;
        float acc = 0.f;
        #pragma unroll 8
        for (int d = 0; d < DD; d++) acc += fr[d]*sw[d];
        att[t] = expf(acc) * fmask[bwf*LF + t];
    }
    __syncthreads();
    if (t == 0) {
        float ss = 0.f;
        for (int l = 0; l < LF; l++) ss += att[l];
        s_inv = 1.f / (ss + 1e-7f);
    }
    __syncthreads();
    float inv = s_inv;
    if (t < LF) out[OUT_SELFATT + bwf*LF + t] = att[t]*inv;
    float acc = 0.f;
    #pragma unroll 8
    for (int l = 0; l < LF; l++) acc += att[l]*inv*fbase[l*DD + t];
    out[OUT_FRAGCODE + bwf*DD + t] = acc;
}

// ============================================================
// Probe: keeps k_qf_mma at ncu's fixed capture index 3.
// ============================================================
__global__ void k_probe() { g_probe[threadIdx.x] = 0.f; }

// ============================================================
// Kernel C (hot, HMMA, warp-specialized): per (bwf, lf-quarter16),
// FULL M=128: partial max over lf of (f_att + q @ (f_lf ⊙ W_qf)).
// 640 threads: 16 CONSUMER warps (MMA; m-strip 16 x n-half 32,
// A_hi frags in regs, A_lo from smem) + 4 PRODUCER warps that
// convert B'(lf+1) into a double buffer. Producer/consumer sync
// via named barriers (full: ids 1,2; free: ids 3,4; count 640)
// so conversion overlaps MMA — removes the phase serialization
// that capped tensor% at ~35 (r13/r14 profiles).
// ============================================================
// smem word offsets
#define QW_WT   0                       // W transposed [64][130] = 8320
#define QW_AH   8320                    // [128][68] u32 = 8704
#define QW_AL   (QW_AH + 8704)          // [128][68] u32 = 8704
#define QW_B0H  (QW_AL + 8704)          // [64][68] u32 = 4352
#define QW_B0L  (QW_B0H + 4352)
#define QW_B1H  (QW_B0L + 4352)
#define QW_B1L  (QW_B1H + 4352)
#define QW_TOT  (QW_B1L + 4352)         // 43136 words = 172544 B

__global__ void __launch_bounds__(640) k_qf_mma(
    const float* __restrict__ qfW, const float* __restrict__ outq) {
    extern __shared__ float s[];
    float* Wt = s + QW_WT;                       // [v][130] fp32
    uint32_t* Ah = (uint32_t*)(s + QW_AH);       // [row][68]
    uint32_t* Al = (uint32_t*)(s + QW_AL);

    int blk = blockIdx.x;            // 256 = bwf(64) x lfq(4)
    int lfq = blk & 3;
    int bwf = blk >> 2;
    int b = bwf >> 4;
    int lfbase = lfq * 16;
    int tid = threadIdx.x, lane = tid & 31, wid = tid >> 5;

    // prologue (all 640 threads): stage Wt, convert A
    for (int idx = tid; idx < DD*VV; idx += 640) {
        int d = idx >> 6, v = idx & 63;
        Wt[v*130 + d] = qfW[idx];
    }
    for (int idx = tid; idx < 128*64; idx += 640) {
        int row = idx >> 6, cp = idx & 63;
        float2 qv = *(const float2*)&outq[((size_t)(b*LQ + row))*DD + cp*2];
        uint32_t hi, lo;
        split2(qv.x, qv.y, hi, lo);
        Ah[row*68 + cp] = hi;
        Al[row*68 + cp] = lo;
    }
    __syncthreads();

    if (wid < 16) {
        // ---------------- CONSUMER: MMA ----------------
        int m0 = (wid & 7) * 16;         // m-strip within 128
        int n0 = (wid >> 3) * 32;        // n-half
        int rfrag = m0 + (lane >> 2);

        uint32_t ah[8][4];
        #pragma unroll
        for (int k = 0; k < 8; k++) {
            int c = k*8 + (lane & 3);
            ah[k][0] = Ah[rfrag*68 + c];       ah[k][1] = Ah[(rfrag+8)*68 + c];
            ah[k][2] = Ah[rfrag*68 + c + 4];   ah[k][3] = Ah[(rfrag+8)*68 + c + 4];
        }

        float mx[4][4];
        #pragma unroll
        for (int t = 0; t < 4; t++)
            #pragma unroll
            for (int i = 0; i < 4; i++) mx[t][i] = -INFINITY;

        for (int k16 = 0; k16 < 16; k16++) {
            int buf = k16 & 1;
            BAR_SYNC(1 + buf, 640);                       // wait B'(lf) full
            const uint32_t* Bh = (const uint32_t*)(s + (buf ? QW_B1H : QW_B0H));
            const uint32_t* Bl = (const uint32_t*)(s + (buf ? QW_B1L : QW_B0L));

            float cc[4][4];
            #pragma unroll
            for (int t = 0; t < 4; t++)
                #pragma unroll
                for (int i = 0; i < 4; i++) cc[t][i] = 0.f;

            #pragma unroll
            for (int k = 0; k < 8; k++) {
                int c = k*8 + (lane & 3);
                uint32_t alk[4];
                alk[0] = Al[rfrag*68 + c];       alk[1] = Al[(rfrag+8)*68 + c];
                alk[2] = Al[rfrag*68 + c + 4];   alk[3] = Al[(rfrag+8)*68 + c + 4];
                #pragma unroll
                for (int t = 0; t < 4; t++) {
                    int v = n0 + t*8 + (lane >> 2);
                    uint32_t bh[2], bl[2];
                    bh[0] = Bh[v*68 + c];  bh[1] = Bh[v*68 + c + 4];
                    bl[0] = Bl[v*68 + c];  bl[1] = Bl[v*68 + c + 4];
                    mma16816(cc[t], ah[k], bh);
                    mma16816(cc[t], ah[k], bl);
                    mma16816(cc[t], alk,   bh);
                }
            }

            const float* fa = g_fatt + ((size_t)bwf*LF + lfbase + k16)*VV;
            #pragma unroll
            for (int t = 0; t < 4; t++) {
                int col = n0 + t*8 + (lane & 3)*2;
                float2 f2 = *(const float2*)&fa[col];
                mx[t][0] = fmaxf(mx[t][0], cc[t][0] + f2.x);
                mx[t][1] = fmaxf(mx[t][1], cc[t][1] + f2.y);
                mx[t][2] = fmaxf(mx[t][2], cc[t][2] + f2.x);
                mx[t][3] = fmaxf(mx[t][3], cc[t][3] + f2.y);
            }

            if (k16 <= 13) BAR_ARRIVE(3 + buf, 640);      // release buffer
        }

        // write partial-max tile [128][64]
        float* outp = g_pmax + (size_t)blk * (LQ*VV);
        #pragma unroll
        for (int t = 0; t < 4; t++) {
            int col = n0 + t*8 + (lane & 3)*2;
            *(float2*)&outp[rfrag*64 + col]     = make_float2(mx[t][0], mx[t][1]);
            *(float2*)&outp[(rfrag+8)*64 + col] = make_float2(mx[t][2], mx[t][3]);
        }
    } else {
        // ---------------- PRODUCER: B' conversion ----------------
        int ptid = tid - 512;            // 0..127
        for (int k16 = 0; k16 < 16; k16++) {
            int buf = k16 & 1;
            if (k16 >= 2) BAR_SYNC(3 + buf, 640);         // wait buffer free
            uint32_t* Bh = (uint32_t*)(s + (buf ? QW_B1H : QW_B0H));
            uint32_t* Bl = (uint32_t*)(s + (buf ? QW_B1L : QW_B0L));
            const float* fptr = g_fproj + ((size_t)bwf*LF + lfbase + k16)*DD;
            #pragma unroll
            for (int i = 0; i < 32; i++) {
                int idx = ptid + 128*i;
                int v = idx >> 6, cp = idx & 63;
                float2 wv = *(const float2*)&Wt[v*130 + cp*2];
                float2 fv = *(const float2*)&fptr[cp*2];
                uint32_t hi, lo;
                split2(wv.x*fv.x, wv.y*fv.y, hi, lo);
                Bh[v*68 + cp] = hi;
                Bl[v*68 + cp] = lo;
            }
            BAR_ARRIVE(1 + buf, 640);                     // publish full
        }
    }
}

// ============================================================
// Kernel D: fused finalize, 512 threads, ONE launch.
// pmax layout [bwf*4+lfq][128][64].
// ============================================================
__global__ void __launch_bounds__(512) k_fin(
    const float* __restrict__ gate_w,
    const float* __restrict__ val_w,
    const float* __restrict__ qmask,
    const float* __restrict__ outq,
    float* __restrict__ out) {
    int bwf = blockIdx.x;
    int b = bwf >> 4;
    int tid = threadIdx.x;
    int lq = tid & 127, vq = tid >> 7;
    __shared__ float gsh[4][LQ];
    __shared__ float vsh[4][LQ];
    __shared__ float esh[LQ];
    __shared__ float red[LQ];
    __shared__ float inv_s;

    {
        const float* base = g_pmax + (size_t)(bwf*4) * (LQ*VV) + lq*VV;
        const float4* qa = (const float4*)(g_qatt + (size_t)(b*LQ + lq)*VV);
        const float4* gw = (const float4*)gate_w;
        const float4* vw = (const float4*)val_w;
        float gs = 0.f, vs = 0.f;
        #pragma unroll
        for (int i = vq*4; i < vq*4 + 4; i++) {
            float4 a0 = *(const float4*)&base[i*4];
            float4 a1 = *(const float4*)&base[LQ*VV + i*4];
            float4 a2 = *(const float4*)&base[2*LQ*VV + i*4];
            float4 a3 = *(const float4*)&base[3*LQ*VV + i*4];
            float4 q = qa[i], g4 = gw[i], v4 = vw[i];
            float mxv = fmaxf(fmaxf(a0.x, a1.x), fmaxf(a2.x, a3.x)) + q.x;
            float myv = fmaxf(fmaxf(a0.y, a1.y), fmaxf(a2.y, a3.y)) + q.y;
            float mzv = fmaxf(fmaxf(a0.z, a1.z), fmaxf(a2.z, a3.z)) + q.z;
            float mwv = fmaxf(fmaxf(a0.w, a1.w), fmaxf(a2.w, a3.w)) + q.w;
            gs += mxv*g4.x + myv*g4.y + mzv*g4.z + mwv*g4.w;
            vs += mxv*v4.x + myv*v4.y + mzv*v4.z + mwv*v4.w;
        }
        gsh[vq][lq] = gs;
        vsh[vq][lq] = vs;
    }
    __syncthreads();

    if (tid < LQ) {
        float gsum = gsh[0][tid] + gsh[1][tid] + gsh[2][tid] + gsh[3][tid];
        float vsum = vsh[0][tid] + vsh[1][tid] + vsh[2][tid] + vsh[3][tid];
        float qm = qmask[b*LQ + tid];
        out[OUT_GATE + bwf*LQ + tid] = (1.f / (1.f + expf(-gsum))) * qm;
        float e2 = expf(vsum) * qm;
        esh[tid] = e2;
        red[tid] = e2;
    }
    __syncthreads();
    #pragma unroll
    for (int off = 64; off > 0; off >>= 1) {
        if (tid < off) red[tid] += red[tid + off];
        __syncthreads();
    }
    if (tid == 0) inv_s = 1.f / (red[0] + 1e-7f);
    __syncthreads();

    {
        int d = lq;
        const float* qb = outq + ((size_t)(b*LQ + vq*32))*DD + d;
        float acc = 0.f;
        #pragma unroll 8
        for (int l = 0; l < 32; l++)
            acc = fmaf(esh[vq*32 + l], qb[(size_t)l*DD], acc);
        gsh[vq][d] = acc;
    }
    __syncthreads();
    if (tid < LQ) {
        float qc = gsh[0][tid] + gsh[1][tid] + gsh[2][tid] + gsh[3][tid];
        out[OUT_QUERYCODE + bwf*DD + tid] = qc * inv_s;
    }
}

// ============================================================
extern "C" void kernel_launch(void* const* d_in, const int* in_sizes, int n_in,
                              void* d_out, int out_size) {
    const float* query    = (const float*)d_in[0];
    const float* fragment = (const float*)d_in[1];
    const float* qmask    = (const float*)d_in[2];
    const float* fmask    = (const float*)d_in[3];
    const float* projW    = (const float*)d_in[4];
    const float* projb    = (const float*)d_in[5];
    const float* saW      = (const float*)d_in[6];
    const float* qattW    = (const float*)d_in[7];
    const float* fattW    = (const float*)d_in[8];
    const float* qfW      = (const float*)d_in[9];
    const float* gatew    = (const float*)d_in[10];
    const float* valw     = (const float*)d_in[11];
    float* out = (float*)d_out;
    float* outq = out + OUT_QUERY;

    const int smemPA = 26624 * (int)sizeof(float);   // 106496
    const int smemQF = QW_TOT * (int)sizeof(float);  // 172544
    cudaFuncSetAttribute(k_projatt, cudaFuncAttributeMaxDynamicSharedMemorySize, smemPA);
    cudaFuncSetAttribute(k_qf_mma, cudaFuncAttributeMaxDynamicSharedMemorySize, smemQF);

    k_projatt<<<576, 256, smemPA>>>(query, fragment, projW, projb, qattW, fattW, outq);  // idx 0
    k_fragcode<<<BB*WF, 128>>>(saW, fmask, out);                                          // idx 1
    k_probe<<<1, 32>>>();                                                                 // idx 2
    k_qf_mma<<<256, 640, smemQF>>>(qfW, outq);                                            // idx 3 (profiled)
    k_fin<<<BB*WF, 512>>>(gatew, valw, qmask, outq, out);                                 // idx 4
}

// round 16
// speedup vs baseline: 1.0769x; 1.0111x over previous
#include <cuda_runtime.h>
#include <cuda_bf16.h>
#include <math.h>
#include <stdint.h>

#define BB 4
#define LQ 128
#define LF 64
#define NW 2
#define NFR 8
#define EE 128
#define DD 128
#define VV 64
#define WF (NW*NFR)   // 16

// ---- output layout (concatenated in reference tuple order) ----
#define OUT_FRAGCODE  0
#define OUT_QUERYCODE (BB*WF*DD)
#define OUT_SELFATT   (2*BB*WF*DD)
#define OUT_GATE      (2*BB*WF*DD + BB*WF*LF)
#define OUT_QUERY     (OUT_GATE + BB*WF*LQ)

// ---- scratch ----
__device__ float g_fproj[BB*WF*LF*DD];   // projected fragment (b,wf,lf,d)
__device__ float g_qatt [BB*LQ*VV];      // q_att (b,lq,v)
__device__ float g_fatt [BB*WF*LF*VV];   // f_att (b,wf,lf,v)
__device__ float g_pmax [256*LQ*VV];     // partial maxes [bwf*4+lfq][128][64] (8MB)
__device__ float g_probe[32];            // probe sink

// bf16 split helpers
__device__ __forceinline__ uint32_t pack_bf16x2(float lo_val, float hi_val) {
    uint32_t r;
    asm("cvt.rn.bf16x2.f32 %0, %1, %2;" : "=r"(r) : "f"(hi_val), "f"(lo_val));
    return r;
}
__device__ __forceinline__ float bf16lo_f32(uint32_t u) { return __uint_as_float(u << 16); }
__device__ __forceinline__ float bf16hi_f32(uint32_t u) { return __uint_as_float(u & 0xffff0000u); }
__device__ __forceinline__ void split2(float x0, float x1, uint32_t& hi, uint32_t& lo) {
    hi = pack_bf16x2(x0, x1);
    float r0 = x0 - bf16lo_f32(hi);
    float r1 = x1 - bf16hi_f32(hi);
    lo = pack_bf16x2(r0, r1);
}

// mma.sync m16n8k16 row.col f32.bf16.bf16.f32
__device__ __forceinline__ void mma16816(float* c, const uint32_t* a, const uint32_t* b) {
    asm volatile(
        "mma.sync.aligned.m16n8k16.row.col.f32.bf16.bf16.f32 "
        "{%0,%1,%2,%3}, {%4,%5,%6,%7}, {%8,%9}, {%0,%1,%2,%3};"
        : "+f"(c[0]), "+f"(c[1]), "+f"(c[2]), "+f"(c[3])
        : "r"(a[0]), "r"(a[1]), "r"(a[2]), "r"(a[3]), "r"(b[0]), "r"(b[1]));
}

// named barriers (CUTLASS producer/consumer pattern)
#define BAR_SYNC(id, cnt)   asm volatile("bar.sync %0, %1;"   :: "r"(id), "r"(cnt) : "memory")
#define BAR_ARRIVE(id, cnt) asm volatile("bar.arrive %0, %1;" :: "r"(id), "r"(cnt) : "memory")

// ============================================================
// Kernel A: fused projection + attention-weight GEMMs, tiled.
// ============================================================
__global__ void __launch_bounds__(256) k_projatt(
    const float* __restrict__ query, const float* __restrict__ frag,
    const float* __restrict__ W, const float* __restrict__ bias,
    const float* __restrict__ qattW, const float* __restrict__ fattW,
    float* __restrict__ outq) {
    extern __shared__ float s[];
    float* Wsh  = s;            // 16384
    float* AWsh = s + 16384;    // 8192
    float* xsh  = s + 24576;    // 1024
    float* psh  = s + 25600;    // 1024   total 26624 floats
    int g = blockIdx.x;
    int tid = threadIdx.x;
    bool isq = (g < 64);

    {
        const float4* Wv = (const float4*)W;
        float4* Ws = (float4*)Wsh;
        #pragma unroll
        for (int i = 0; i < 16; i++) Ws[tid + 256*i] = Wv[tid + 256*i];
        const float4* Av = (const float4*)(isq ? qattW : fattW);
        float4* As = (float4*)AWsh;
        #pragma unroll
        for (int i = 0; i < 8; i++) As[tid + 256*i] = Av[tid + 256*i];
        const float* src = isq ? (query + (size_t)g*8*EE)
                               : (frag  + (size_t)(g-64)*8*EE);
        ((float4*)xsh)[tid] = ((const float4*)src)[tid];
    }
    __syncthreads();

    {
        int j = tid & 127, rh = tid >> 7;
        float bj = __ldg(&bias[j]);
        float a0 = bj, a1 = bj, a2 = bj, a3 = bj;
        #pragma unroll 4
        for (int d = 0; d < EE; d++) {
            float w = Wsh[d*DD + j];
            a0 = fmaf(xsh[(rh+0)*EE + d], w, a0);
            a1 = fmaf(xsh[(rh+2)*EE + d], w, a1);
            a2 = fmaf(xsh[(rh+4)*EE + d], w, a2);
            a3 = fmaf(xsh[(rh+6)*EE + d], w, a3);
        }
        psh[(rh+0)*DD + j] = a0; psh[(rh+2)*DD + j] = a1;
        psh[(rh+4)*DD + j] = a2; psh[(rh+6)*DD + j] = a3;
        float* dst = isq ? (outq + (size_t)g*8*DD)
                         : (g_fproj + (size_t)(g-64)*8*DD);
        dst[(rh+0)*DD + j] = a0; dst[(rh+2)*DD + j] = a1;
        dst[(rh+4)*DD + j] = a2; dst[(rh+6)*DD + j] = a3;
    }
    __syncthreads();

    {
        int j2 = tid & 63, r2 = tid >> 6;
        float a0 = 0.f, a1 = 0.f;
        #pragma unroll 4
        for (int d = 0; d < DD; d++) {
            float w = AWsh[d*VV + j2];
            a0 = fmaf(psh[(r2+0)*DD + d], w, a0);
            a1 = fmaf(psh[(r2+4)*DD + d], w, a1);
        }
        float* dst = isq ? (g_qatt + (size_t)g*8*VV)
                         : (g_fatt + (size_t)(g-64)*8*VV);
        dst[(r2+0)*VV + j2] = a0;
        dst[(r2+4)*VV + j2] = a1;
    }
}

// ============================================================
// Kernel B: fragment self-attention softmax + frag_code
// ============================================================
__global__ void k_fragcode(const float* __restrict__ saW,
                           const float* __restrict__ fmask,
                           float* __restrict__ out) {
    int bwf = blockIdx.x;
    int w = (bwf % WF) / NFR;
    const float* fbase = g_fproj + (size_t)bwf*LF*DD;
    __shared__ float att[LF];
    __shared__ float s_inv;
    int t = threadIdx.x;
    if (t < LF) {
        const float* fr = fbase + t*DD;
        const float* sw = saW + w*DD;
        float acc = 0.f;
        #pragma unroll 8
        for (int d = 0; d < DD; d++) acc += fr[d]*sw[d];
        att[t] = expf(acc) * fmask[bwf*LF + t];
    }
    __syncthreads();
    if (t == 0) {
        float ss = 0.f;
        for (int l = 0; l < LF; l++) ss += att[l];
        s_inv = 1.f / (ss + 1e-7f);
    }
    __syncthreads();
    float inv = s_inv;
    if (t < LF) out[OUT_SELFATT + bwf*LF + t] = att[t]*inv;
    float acc = 0.f;
    #pragma unroll 8
    for (int l = 0; l < LF; l++) acc += att[l]*inv*fbase[l*DD + t];
    out[OUT_FRAGCODE + bwf*DD + t] = acc;
}

// ============================================================
// Probe: keeps k_qf_mma at ncu's fixed capture index 3.
// ============================================================
__global__ void k_probe() { g_probe[threadIdx.x] = 0.f; }

// ============================================================
// Kernel C (hot, HMMA, warp-specialized): per (bwf, lf-quarter16),
// FULL M=128: partial max over lf of (f_att + q @ (f_lf ⊙ W_qf)).
// 640 threads: 16 CONSUMER warps + 4 PRODUCER warps (named-barrier
// double buffer, as r15). NEW: pass-major MMA schedule within each
// k — all bh[t] loaded first, then ah·bh across t, alk·bh across t,
// ah·bl across t. Same-accumulator dependency distance 1 -> 4.
// ============================================================
// smem word offsets
#define QW_WT   0                       // W transposed [64][130] = 8320
#define QW_AH   8320                    // [128][68] u32 = 8704
#define QW_AL   (QW_AH + 8704)          // [128][68] u32 = 8704
#define QW_B0H  (QW_AL + 8704)          // [64][68] u32 = 4352
#define QW_B0L  (QW_B0H + 4352)
#define QW_B1H  (QW_B0L + 4352)
#define QW_B1L  (QW_B1H + 4352)
#define QW_TOT  (QW_B1L + 4352)         // 43136 words = 172544 B

__global__ void __launch_bounds__(640) k_qf_mma(
    const float* __restrict__ qfW, const float* __restrict__ outq) {
    extern __shared__ float s[];
    float* Wt = s + QW_WT;                       // [v][130] fp32
    uint32_t* Ah = (uint32_t*)(s + QW_AH);       // [row][68]
    uint32_t* Al = (uint32_t*)(s + QW_AL);

    int blk = blockIdx.x;            // 256 = bwf(64) x lfq(4)
    int lfq = blk & 3;
    int bwf = blk >> 2;
    int b = bwf >> 4;
    int lfbase = lfq * 16;
    int tid = threadIdx.x, lane = tid & 31, wid = tid >> 5;

    // prologue (all 640 threads): stage Wt, convert A
    for (int idx = tid; idx < DD*VV; idx += 640) {
        int d = idx >> 6, v = idx & 63;
        Wt[v*130 + d] = qfW[idx];
    }
    for (int idx = tid; idx < 128*64; idx += 640) {
        int row = idx >> 6, cp = idx & 63;
        float2 qv = *(const float2*)&outq[((size_t)(b*LQ + row))*DD + cp*2];
        uint32_t hi, lo;
        split2(qv.x, qv.y, hi, lo);
        Ah[row*68 + cp] = hi;
        Al[row*68 + cp] = lo;
    }
    __syncthreads();

    if (wid < 16) {
        // ---------------- CONSUMER: MMA ----------------
        int m0 = (wid & 7) * 16;         // m-strip within 128
        int n0 = (wid >> 3) * 32;        // n-half
        int rfrag = m0 + (lane >> 2);

        uint32_t ah[8][4];
        #pragma unroll
        for (int k = 0; k < 8; k++) {
            int c = k*8 + (lane & 3);
            ah[k][0] = Ah[rfrag*68 + c];       ah[k][1] = Ah[(rfrag+8)*68 + c];
            ah[k][2] = Ah[rfrag*68 + c + 4];   ah[k][3] = Ah[(rfrag+8)*68 + c + 4];
        }

        float mx[4][4];
        #pragma unroll
        for (int t = 0; t < 4; t++)
            #pragma unroll
            for (int i = 0; i < 4; i++) mx[t][i] = -INFINITY;

        for (int k16 = 0; k16 < 16; k16++) {
            int buf = k16 & 1;
            BAR_SYNC(1 + buf, 640);                       // wait B'(lf) full
            const uint32_t* Bh = (const uint32_t*)(s + (buf ? QW_B1H : QW_B0H));
            const uint32_t* Bl = (const uint32_t*)(s + (buf ? QW_B1L : QW_B0L));

            float cc[4][4];
            #pragma unroll
            for (int t = 0; t < 4; t++)
                #pragma unroll
                for (int i = 0; i < 4; i++) cc[t][i] = 0.f;

            #pragma unroll
            for (int k = 0; k < 8; k++) {
                int c = k*8 + (lane & 3);
                uint32_t alk[4];
                alk[0] = Al[rfrag*68 + c];       alk[1] = Al[(rfrag+8)*68 + c];
                alk[2] = Al[rfrag*68 + c + 4];   alk[3] = Al[(rfrag+8)*68 + c + 4];
                // load all bh[t] first (reused by 2 passes)
                uint32_t bh[4][2];
                #pragma unroll
                for (int t = 0; t < 4; t++) {
                    int v = n0 + t*8 + (lane >> 2);
                    bh[t][0] = Bh[v*68 + c];  bh[t][1] = Bh[v*68 + c + 4];
                }
                // pass 1: ah·bh — 4 independent accumulator chains
                #pragma unroll
                for (int t = 0; t < 4; t++) mma16816(cc[t], ah[k], bh[t]);
                // pass 2: alk·bh — distance 4 from pass 1 writes
                #pragma unroll
                for (int t = 0; t < 4; t++) mma16816(cc[t], alk, bh[t]);
                // pass 3: ah·bl — loads then 4 independent chains
                uint32_t bl[4][2];
                #pragma unroll
                for (int t = 0; t < 4; t++) {
                    int v = n0 + t*8 + (lane >> 2);
                    bl[t][0] = Bl[v*68 + c];  bl[t][1] = Bl[v*68 + c + 4];
                }
                #pragma unroll
                for (int t = 0; t < 4; t++) mma16816(cc[t], ah[k], bl[t]);
            }

            const float* fa = g_fatt + ((size_t)bwf*LF + lfbase + k16)*VV;
            #pragma unroll
            for (int t = 0; t < 4; t++) {
                int col = n0 + t*8 + (lane & 3)*2;
                float2 f2 = *(const float2*)&fa[col];
                mx[t][0] = fmaxf(mx[t][0], cc[t][0] + f2.x);
                mx[t][1] = fmaxf(mx[t][1], cc[t][1] + f2.y);
                mx[t][2] = fmaxf(mx[t][2], cc[t][2] + f2.x);
                mx[t][3] = fmaxf(mx[t][3], cc[t][3] + f2.y);
            }

            if (k16 <= 13) BAR_ARRIVE(3 + buf, 640);      // release buffer
        }

        // write partial-max tile [128][64]
        float* outp = g_pmax + (size_t)blk * (LQ*VV);
        #pragma unroll
        for (int t = 0; t < 4; t++) {
            int col = n0 + t*8 + (lane & 3)*2;
            *(float2*)&outp[rfrag*64 + col]     = make_float2(mx[t][0], mx[t][1]);
            *(float2*)&outp[(rfrag+8)*64 + col] = make_float2(mx[t][2], mx[t][3]);
        }
    } else {
        // ---------------- PRODUCER: B' conversion ----------------
        int ptid = tid - 512;            // 0..127
        for (int k16 = 0; k16 < 16; k16++) {
            int buf = k16 & 1;
            if (k16 >= 2) BAR_SYNC(3 + buf, 640);         // wait buffer free
            uint32_t* Bh = (uint32_t*)(s + (buf ? QW_B1H : QW_B0H));
            uint32_t* Bl = (uint32_t*)(s + (buf ? QW_B1L : QW_B0L));
            const float* fptr = g_fproj + ((size_t)bwf*LF + lfbase + k16)*DD;
            #pragma unroll
            for (int i = 0; i < 32; i++) {
                int idx = ptid + 128*i;
                int v = idx >> 6, cp = idx & 63;
                float2 wv = *(const float2*)&Wt[v*130 + cp*2];
                float2 fv = *(const float2*)&fptr[cp*2];
                uint32_t hi, lo;
                split2(wv.x*fv.x, wv.y*fv.y, hi, lo);
                Bh[v*68 + cp] = hi;
                Bl[v*68 + cp] = lo;
            }
            BAR_ARRIVE(1 + buf, 640);                     // publish full
        }
    }
}

// ============================================================
// Kernel D: fused finalize, 512 threads, ONE launch.
// pmax layout [bwf*4+lfq][128][64].
// ============================================================
__global__ void __launch_bounds__(512) k_fin(
    const float* __restrict__ gate_w,
    const float* __restrict__ val_w,
    const float* __restrict__ qmask,
    const float* __restrict__ outq,
    float* __restrict__ out) {
    int bwf = blockIdx.x;
    int b = bwf >> 4;
    int tid = threadIdx.x;
    int lq = tid & 127, vq = tid >> 7;
    __shared__ float gsh[4][LQ];
    __shared__ float vsh[4][LQ];
    __shared__ float esh[LQ];
    __shared__ float red[LQ];
    __shared__ float inv_s;

    {
        const float* base = g_pmax + (size_t)(bwf*4) * (LQ*VV) + lq*VV;
        const float4* qa = (const float4*)(g_qatt + (size_t)(b*LQ + lq)*VV);
        const float4* gw = (const float4*)gate_w;
        const float4* vw = (const float4*)val_w;
        float gs = 0.f, vs = 0.f;
        #pragma unroll
        for (int i = vq*4; i < vq*4 + 4; i++) {
            float4 a0 = *(const float4*)&base[i*4];
            float4 a1 = *(const float4*)&base[LQ*VV + i*4];
            float4 a2 = *(const float4*)&base[2*LQ*VV + i*4];
            float4 a3 = *(const float4*)&base[3*LQ*VV + i*4];
            float4 q = qa[i], g4 = gw[i], v4 = vw[i];
            float mxv = fmaxf(fmaxf(a0.x, a1.x), fmaxf(a2.x, a3.x)) + q.x;
            float myv = fmaxf(fmaxf(a0.y, a1.y), fmaxf(a2.y, a3.y)) + q.y;
            float mzv = fmaxf(fmaxf(a0.z, a1.z), fmaxf(a2.z, a3.z)) + q.z;
            float mwv = fmaxf(fmaxf(a0.w, a1.w), fmaxf(a2.w, a3.w)) + q.w;
            gs += mxv*g4.x + myv*g4.y + mzv*g4.z + mwv*g4.w;
            vs += mxv*v4.x + myv*v4.y + mzv*v4.z + mwv*v4.w;
        }
        gsh[vq][lq] = gs;
        vsh[vq][lq] = vs;
    }
    __syncthreads();

    if (tid < LQ) {
        float gsum = gsh[0][tid] + gsh[1][tid] + gsh[2][tid] + gsh[3][tid];
        float vsum = vsh[0][tid] + vsh[1][tid] + vsh[2][tid] + vsh[3][tid];
        float qm = qmask[b*LQ + tid];
        out[OUT_GATE + bwf*LQ + tid] = (1.f / (1.f + expf(-gsum))) * qm;
        float e2 = expf(vsum) * qm;
        esh[tid] = e2;
        red[tid] = e2;
    }
    __syncthreads();
    #pragma unroll
    for (int off = 64; off > 0; off >>= 1) {
        if (tid < off) red[tid] += red[tid + off];
        __syncthreads();
    }
    if (tid == 0) inv_s = 1.f / (red[0] + 1e-7f);
    __syncthreads();

    {
        int d = lq;
        const float* qb = outq + ((size_t)(b*LQ + vq*32))*DD + d;
        float acc = 0.f;
        #pragma unroll 8
        for (int l = 0; l < 32; l++)
            acc = fmaf(esh[vq*32 + l], qb[(size_t)l*DD], acc);
        gsh[vq][d] = acc;
    }
    __syncthreads();
    if (tid < LQ) {
        float qc = gsh[0][tid] + gsh[1][tid] + gsh[2][tid] + gsh[3][tid];
        out[OUT_QUERYCODE + bwf*DD + tid] = qc * inv_s;
    }
}

// ============================================================
extern "C" void kernel_launch(void* const* d_in, const int* in_sizes, int n_in,
                              void* d_out, int out_size) {
    const float* query    = (const float*)d_in[0];
    const float* fragment = (const float*)d_in[1];
    const float* qmask    = (const float*)d_in[2];
    const float* fmask    = (const float*)d_in[3];
    const float* projW    = (const float*)d_in[4];
    const float* projb    = (const float*)d_in[5];
    const float* saW      = (const float*)d_in[6];
    const float* qattW    = (const float*)d_in[7];
    const float* fattW    = (const float*)d_in[8];
    const float* qfW      = (const float*)d_in[9];
    const float* gatew    = (const float*)d_in[10];
    const float* valw     = (const float*)d_in[11];
    float* out = (float*)d_out;
    float* outq = out + OUT_QUERY;

    const int smemPA = 26624 * (int)sizeof(float);   // 106496
    const int smemQF = QW_TOT * (int)sizeof(float);  // 172544
    cudaFuncSetAttribute(k_projatt, cudaFuncAttributeMaxDynamicSharedMemorySize, smemPA);
    cudaFuncSetAttribute(k_qf_mma, cudaFuncAttributeMaxDynamicSharedMemorySize, smemQF);

    k_projatt<<<576, 256, smemPA>>>(query, fragment, projW, projb, qattW, fattW, outq);  // idx 0
    k_fragcode<<<BB*WF, 128>>>(saW, fmask, out);                                          // idx 1
    k_probe<<<1, 32>>>();                                                                 // idx 2
    k_qf_mma<<<256, 640, smemQF>>>(qfW, outq);                                            // idx 3 (profiled)
    k_fin<<<BB*WF, 512>>>(gatew, valw, qmask, outq, out);                                 // idx 4
}